// round 2
// baseline (speedup 1.0000x reference)
#include <cuda_runtime.h>

// Problem constants (fixed by the reference):
// B=16, W=256, S=512, F=768, L=4, E=256, V=50000
#define BB 16
#define WW 256
#define SS 512
#define LL 4
#define NW (WW - 1)

// float4 strides inside layers[L, B, S, F/4=192]
#define LSTRIDE (BB * SS * 192)   // 1,572,864
#define BSTRIDE (SS * 192)        //    98,304

// Grid: one block per (b, w) pair = 4096 blocks, 256 threads.
//   threads   0..63 : copy the 256-float embedding row as 64 float4
//   threads 64..255 : each owns one float4 (4 floats) of the F=768 bert slice
//
// No shared memory, no __syncthreads: the softmax over 4 layer weights is
// recomputed per-thread (cached scalar loads) so the 8 streaming LDG.128s
// can issue at block start with nothing in front of them.
__global__ __launch_bounds__(256, 4)
void bert_lexer_fused(
    const int* __restrict__ word_indices,   // [B, W]
    const int* __restrict__ span_starts,    // [B, W-1]
    const int* __restrict__ span_ends,      // [B, W-1]
    const float4* __restrict__ emb4,        // [V, E/4=64]
    const float4* __restrict__ layers4,     // [L, B, S, F/4=192]
    const float* __restrict__ layer_weights,// [L]
    const float* __restrict__ gamma,        // [1]
    float4* __restrict__ out4)              // [B, W, (E+F)/4=256]
{
    const int bw  = blockIdx.x;        // b*W + w
    const int b   = bw >> 8;           // W = 256
    const int w   = bw & (WW - 1);
    const int tid = threadIdx.x;

    float4* __restrict__ outrow = out4 + (size_t)bw * 256;

    if (tid < 64) {
        // Embedding gather: coalesced 64x float4 = 1KB row.
        const int idx = __ldg(word_indices + bw);
        outrow[tid] = emb4[(size_t)idx * 64 + tid];
        return;
    }

    const int t = tid - 64;  // 0..191  -> float4 index within F
    float4 acc = make_float4(0.f, 0.f, 0.f, 0.f);

    if (w > 0) {
        const int si  = b * NW + (w - 1);
        const int ss  = __ldg(span_starts + si);
        const int se  = __ldg(span_ends + si);
        const int len = se - ss;
        if (len > 0) {
            if (len == 2) {
                // Fast path (all spans in this problem): front-batch all 8
                // LDG.128s with nothing ahead of them for max MLP.
                const float4* base = layers4 + (size_t)b * BSTRIDE + (size_t)ss * 192 + t;
                float4 a0 = base[0 * LSTRIDE      ];
                float4 b0 = base[0 * LSTRIDE + 192];
                float4 a1 = base[1 * LSTRIDE      ];
                float4 b1 = base[1 * LSTRIDE + 192];
                float4 a2 = base[2 * LSTRIDE      ];
                float4 b2 = base[2 * LSTRIDE + 192];
                float4 a3 = base[3 * LSTRIDE      ];
                float4 b3 = base[3 * LSTRIDE + 192];

                // Per-thread softmax (cached loads, overlaps with the LDGs above).
                float lw0 = __ldg(layer_weights + 0), lw1 = __ldg(layer_weights + 1);
                float lw2 = __ldg(layer_weights + 2), lw3 = __ldg(layer_weights + 3);
                float g   = __ldg(gamma);
                float m  = fmaxf(fmaxf(lw0, lw1), fmaxf(lw2, lw3));
                float e0 = __expf(lw0 - m), e1 = __expf(lw1 - m);
                float e2 = __expf(lw2 - m), e3 = __expf(lw3 - m);
                float sc = g * 0.5f / (e0 + e1 + e2 + e3);
                float w0 = e0 * sc, w1 = e1 * sc, w2 = e2 * sc, w3 = e3 * sc;

                acc.x = w0*(a0.x+b0.x) + w1*(a1.x+b1.x) + w2*(a2.x+b2.x) + w3*(a3.x+b3.x);
                acc.y = w0*(a0.y+b0.y) + w1*(a1.y+b1.y) + w2*(a2.y+b2.y) + w3*(a3.y+b3.y);
                acc.z = w0*(a0.z+b0.z) + w1*(a1.z+b1.z) + w2*(a2.z+b2.z) + w3*(a3.z+b3.z);
                acc.w = w0*(a0.w+b0.w) + w1*(a1.w+b1.w) + w2*(a2.w+b2.w) + w3*(a3.w+b3.w);
            } else {
                // Generic path (not hit with this dataset, kept for correctness).
                float lw0 = __ldg(layer_weights + 0), lw1 = __ldg(layer_weights + 1);
                float lw2 = __ldg(layer_weights + 2), lw3 = __ldg(layer_weights + 3);
                float g   = __ldg(gamma);
                float m  = fmaxf(fmaxf(lw0, lw1), fmaxf(lw2, lw3));
                float e0 = __expf(lw0 - m), e1 = __expf(lw1 - m);
                float e2 = __expf(lw2 - m), e3 = __expf(lw3 - m);
                float inv = 1.0f / (e0 + e1 + e2 + e3);
                float sw[LL] = {e0 * inv, e1 * inv, e2 * inv, e3 * inv};
                for (int s = ss; s < se; s++) {
                    #pragma unroll
                    for (int l = 0; l < LL; l++) {
                        float4 v = layers4[(size_t)l * LSTRIDE + (size_t)b * BSTRIDE
                                           + (size_t)s * 192 + t];
                        float wl = sw[l];
                        acc.x += wl * v.x; acc.y += wl * v.y;
                        acc.z += wl * v.z; acc.w += wl * v.w;
                    }
                }
                const float sc = g / (float)len;
                acc.x *= sc; acc.y *= sc; acc.z *= sc; acc.w *= sc;
            }
        }
    }
    // w==0 (root) or empty span -> zeros, matching the reference.
    outrow[64 + t] = acc;
}

extern "C" void kernel_launch(void* const* d_in, const int* in_sizes, int n_in,
                              void* d_out, int out_size)
{
    const int*    word_indices  = (const int*)   d_in[0];
    const int*    span_starts   = (const int*)   d_in[1];
    const int*    span_ends     = (const int*)   d_in[2];
    const float4* emb4          = (const float4*)d_in[3];
    const float4* layers4       = (const float4*)d_in[4];
    const float*  layer_weights = (const float*) d_in[5];
    const float*  gamma         = (const float*) d_in[6];
    float4*       out4          = (float4*)      d_out;

    (void)in_sizes; (void)n_in; (void)out_size;

    bert_lexer_fused<<<BB * WW, 256>>>(word_indices, span_starts, span_ends,
                                       emb4, layers4, layer_weights, gamma, out4);
}

// round 3
// speedup vs baseline: 1.0875x; 1.0875x over previous
#include <cuda_runtime.h>

// Problem constants (fixed by the reference):
// B=16, W=256, S=512, F=768, L=4, E=256, V=50000
#define BB 16
#define WW 256
#define SS 512
#define LL 4
#define NW (WW - 1)

// float4 strides inside layers[L, B, S, F/4=192]
#define LSTRIDE (BB * SS * 192)   // 1,572,864
#define BSTRIDE (SS * 192)        //    98,304

// Grid: one block per (b, w) pair = 4096 blocks, 192 threads.
// Every thread owns one float4 (4 floats) of the F=768 bert slice (8 streaming
// LDG.128s, front-batched). Threads 0..63 ADDITIONALLY gather one float4 of the
// E=256 embedding row — no idle/early-exit warps, every warp streams.
__global__ __launch_bounds__(192, 5)
void bert_lexer_fused(
    const int* __restrict__ word_indices,   // [B, W]
    const int* __restrict__ span_starts,    // [B, W-1]
    const int* __restrict__ span_ends,      // [B, W-1]
    const float4* __restrict__ emb4,        // [V, E/4=64]
    const float4* __restrict__ layers4,     // [L, B, S, F/4=192]
    const float* __restrict__ layer_weights,// [L]
    const float* __restrict__ gamma,        // [1]
    float4* __restrict__ out4)              // [B, W, (E+F)/4=256]
{
    const int bw = blockIdx.x;        // b*W + w
    const int b  = bw >> 8;           // W = 256
    const int w  = bw & (WW - 1);
    const int t  = threadIdx.x;       // 0..191 -> float4 index within F

    float4* __restrict__ outrow = out4 + (size_t)bw * 256;

    // ---- embedding gather chain (threads 0..63), issued first: it's the
    // longest dependent chain (idx load -> row load) and independent of bert.
    float4 ev = make_float4(0.f, 0.f, 0.f, 0.f);
    const bool do_emb = (t < 64);
    if (do_emb) {
        const int idx = __ldg(word_indices + bw);
        ev = emb4[(size_t)idx * 64 + t];
    }

    // ---- bert slice: softmax-weighted layer mix averaged over the span
    float4 acc = make_float4(0.f, 0.f, 0.f, 0.f);
    if (w > 0) {
        const int si  = b * NW + (w - 1);
        const int ss  = __ldg(span_starts + si);
        const int se  = __ldg(span_ends + si);
        const int len = se - ss;
        if (len > 0) {
            if (len == 2) {
                // Fast path (all spans in this dataset): front-batch all 8
                // LDG.128s with nothing ahead of them for max MLP.
                const float4* base = layers4 + (size_t)b * BSTRIDE + (size_t)ss * 192 + t;
                float4 a0 = base[0 * LSTRIDE      ];
                float4 b0 = base[0 * LSTRIDE + 192];
                float4 a1 = base[1 * LSTRIDE      ];
                float4 b1 = base[1 * LSTRIDE + 192];
                float4 a2 = base[2 * LSTRIDE      ];
                float4 b2 = base[2 * LSTRIDE + 192];
                float4 a3 = base[3 * LSTRIDE      ];
                float4 b3 = base[3 * LSTRIDE + 192];

                // Per-thread softmax (cached scalar loads, overlap the LDGs).
                float lw0 = __ldg(layer_weights + 0), lw1 = __ldg(layer_weights + 1);
                float lw2 = __ldg(layer_weights + 2), lw3 = __ldg(layer_weights + 3);
                float g   = __ldg(gamma);
                float m  = fmaxf(fmaxf(lw0, lw1), fmaxf(lw2, lw3));
                float e0 = __expf(lw0 - m), e1 = __expf(lw1 - m);
                float e2 = __expf(lw2 - m), e3 = __expf(lw3 - m);
                float sc = g * 0.5f / (e0 + e1 + e2 + e3);
                float w0 = e0 * sc, w1 = e1 * sc, w2 = e2 * sc, w3 = e3 * sc;

                acc.x = w0*(a0.x+b0.x) + w1*(a1.x+b1.x) + w2*(a2.x+b2.x) + w3*(a3.x+b3.x);
                acc.y = w0*(a0.y+b0.y) + w1*(a1.y+b1.y) + w2*(a2.y+b2.y) + w3*(a3.y+b3.y);
                acc.z = w0*(a0.z+b0.z) + w1*(a1.z+b1.z) + w2*(a2.z+b2.z) + w3*(a3.z+b3.z);
                acc.w = w0*(a0.w+b0.w) + w1*(a1.w+b1.w) + w2*(a2.w+b2.w) + w3*(a3.w+b3.w);
            } else {
                // Generic path (not hit with this dataset, kept for correctness).
                float lw0 = __ldg(layer_weights + 0), lw1 = __ldg(layer_weights + 1);
                float lw2 = __ldg(layer_weights + 2), lw3 = __ldg(layer_weights + 3);
                float g   = __ldg(gamma);
                float m  = fmaxf(fmaxf(lw0, lw1), fmaxf(lw2, lw3));
                float e0 = __expf(lw0 - m), e1 = __expf(lw1 - m);
                float e2 = __expf(lw2 - m), e3 = __expf(lw3 - m);
                float inv = 1.0f / (e0 + e1 + e2 + e3);
                float swt[LL] = {e0 * inv, e1 * inv, e2 * inv, e3 * inv};
                for (int s = ss; s < se; s++) {
                    #pragma unroll
                    for (int l = 0; l < LL; l++) {
                        float4 v = layers4[(size_t)l * LSTRIDE + (size_t)b * BSTRIDE
                                           + (size_t)s * 192 + t];
                        float wl = swt[l];
                        acc.x += wl * v.x; acc.y += wl * v.y;
                        acc.z += wl * v.z; acc.w += wl * v.w;
                    }
                }
                const float sc = g / (float)len;
                acc.x *= sc; acc.y *= sc; acc.z *= sc; acc.w *= sc;
            }
        }
    }

    // Stores last: emb store (threads 0..63) + bert store (all threads).
    if (do_emb) outrow[t] = ev;
    outrow[64 + t] = acc;   // w==0 or empty span -> zeros, matching reference
}

extern "C" void kernel_launch(void* const* d_in, const int* in_sizes, int n_in,
                              void* d_out, int out_size)
{
    const int*    word_indices  = (const int*)   d_in[0];
    const int*    span_starts   = (const int*)   d_in[1];
    const int*    span_ends     = (const int*)   d_in[2];
    const float4* emb4          = (const float4*)d_in[3];
    const float4* layers4       = (const float4*)d_in[4];
    const float*  layer_weights = (const float*) d_in[5];
    const float*  gamma         = (const float*) d_in[6];
    float4*       out4          = (float4*)      d_out;

    (void)in_sizes; (void)n_in; (void)out_size;

    bert_lexer_fused<<<BB * WW, 192>>>(word_indices, span_starts, span_ends,
                                       emb4, layers4, layer_weights, gamma, out4);
}